// round 7
// baseline (speedup 1.0000x reference)
#include <cuda_runtime.h>
#include <cuda_bf16.h>

// x = (N=2, C=16, D=96, H=128, W=128) fp32; out = concat(gx, gy, gz).
// 3-way output split: sibling CTAs (adjacent blockIdx.x) compute gx / gy / gz
// for the same tile, sharing input reads through L2.

#define W_   128
#define H_   128
#define D_   96
#define NC_  32
#define YT_  8
#define HW_  (H_ * W_)
#define CST_ (D_ * HW_)
#define V_   (NC_ * CST_)

__device__ __forceinline__ float4 ld4z(const float* p, bool ok) {
    if (ok) return *reinterpret_cast<const float4*>(p);
    return make_float4(0.f, 0.f, 0.f, 0.f);
}

__global__ __launch_bounds__(256, 5)
void sobel3d_kernel(const float* __restrict__ in, float* __restrict__ out) {
    const int variant = blockIdx.x % 3;              // 0:gx 1:gy 2:gz
    const int yt      = blockIdx.x / 3;
    const int nc      = blockIdx.y;
    const int lane    = threadIdx.x;
    const int y       = yt * YT_ + threadIdx.y;
    const int x4      = lane * 4;

    const float* src = in + nc * CST_;
    const bool ym_ok = (y > 0);
    const bool yp_ok = (y < H_ - 1);
    const int rm_off = (y - 1) * W_ + x4;
    const int r0_off = y * W_ + x4;
    const int rp_off = (y + 1) * W_ + x4;
    float* dst = out + variant * V_ + nc * CST_ + y * W_ + x4;

    if (variant == 1) {
        // ---- gy = smooth_x( smooth_z( deriv_y ) ) : needs rows y-1, y+1 only
        float4 zz = make_float4(0.f, 0.f, 0.f, 0.f);
        float4 d_m = zz, d_0 = zz;
        float4 f_m = ld4z(src + rm_off, ym_ok);
        float4 f_p = ld4z(src + rp_off, yp_ok);

        #pragma unroll 2
        for (int pz = 0; pz <= D_; ++pz) {
            float4 d_p;
            d_p.x = f_p.x - f_m.x; d_p.y = f_p.y - f_m.y;
            d_p.z = f_p.z - f_m.z; d_p.w = f_p.w - f_m.w;

            if (pz < D_) {
                const bool zin = (pz + 1) < D_;
                const float* pl = src + (pz + 1) * HW_;
                f_m = ld4z(pl + rm_off, zin && ym_ok);
                f_p = ld4z(pl + rp_off, zin && yp_ok);
            }

            if (pz >= 1) {
                float4 Dz;
                Dz.x = d_m.x + 2.f * d_0.x + d_p.x;
                Dz.y = d_m.y + 2.f * d_0.y + d_p.y;
                Dz.z = d_m.z + 2.f * d_0.z + d_p.z;
                Dz.w = d_m.w + 2.f * d_0.w + d_p.w;
                float L = __shfl_up_sync(0xffffffffu, Dz.w, 1);
                float R = __shfl_down_sync(0xffffffffu, Dz.x, 1);
                if (lane == 0)  L = 0.f;
                if (lane == 31) R = 0.f;
                float4 v;
                v.x = L    + 2.f * Dz.x + Dz.y;
                v.y = Dz.x + 2.f * Dz.y + Dz.z;
                v.z = Dz.y + 2.f * Dz.z + Dz.w;
                v.w = Dz.z + 2.f * Dz.w + R;
                __stcs(reinterpret_cast<float4*>(dst + (pz - 1) * HW_), v);
            }
            d_m = d_0; d_0 = d_p;
        }
    } else {
        // ---- s-ring variants: s = smooth_y needs all 3 rows
        float4 zz = make_float4(0.f, 0.f, 0.f, 0.f);
        float4 s_m = zz, s_0 = zz;
        float4 f_m = ld4z(src + rm_off, ym_ok);
        float4 f_0 = *reinterpret_cast<const float4*>(src + r0_off);
        float4 f_p = ld4z(src + rp_off, yp_ok);

        #pragma unroll 2
        for (int pz = 0; pz <= D_; ++pz) {
            float4 s_p;
            s_p.x = f_m.x + 2.f * f_0.x + f_p.x;
            s_p.y = f_m.y + 2.f * f_0.y + f_p.y;
            s_p.z = f_m.z + 2.f * f_0.z + f_p.z;
            s_p.w = f_m.w + 2.f * f_0.w + f_p.w;

            if (pz < D_) {
                const bool zin = (pz + 1) < D_;
                const float* pl = src + (pz + 1) * HW_;
                f_m = ld4z(pl + rm_off, zin && ym_ok);
                f_0 = ld4z(pl + r0_off, zin);
                f_p = ld4z(pl + rp_off, zin && yp_ok);
            }

            if (pz >= 1) {
                float4 C;
                if (variant == 0) {
                    // gx = deriv_x( smooth_z( smooth_y ) )
                    C.x = s_m.x + 2.f * s_0.x + s_p.x;
                    C.y = s_m.y + 2.f * s_0.y + s_p.y;
                    C.z = s_m.z + 2.f * s_0.z + s_p.z;
                    C.w = s_m.w + 2.f * s_0.w + s_p.w;
                } else {
                    // gz = smooth_x( deriv_z( smooth_y ) )
                    C.x = s_p.x - s_m.x; C.y = s_p.y - s_m.y;
                    C.z = s_p.z - s_m.z; C.w = s_p.w - s_m.w;
                }
                float L = __shfl_up_sync(0xffffffffu, C.w, 1);
                float R = __shfl_down_sync(0xffffffffu, C.x, 1);
                if (lane == 0)  L = 0.f;
                if (lane == 31) R = 0.f;
                float4 v;
                if (variant == 0) {
                    v.x = C.y - L;   v.y = C.z - C.x;
                    v.z = C.w - C.y; v.w = R   - C.z;
                } else {
                    v.x = L   + 2.f * C.x + C.y;
                    v.y = C.x + 2.f * C.y + C.z;
                    v.z = C.y + 2.f * C.z + C.w;
                    v.w = C.z + 2.f * C.w + R;
                }
                __stcs(reinterpret_cast<float4*>(dst + (pz - 1) * HW_), v);
            }
            s_m = s_0; s_0 = s_p;
        }
    }
}

extern "C" void kernel_launch(void* const* d_in, const int* in_sizes, int n_in,
                              void* d_out, int out_size) {
    const float* x = (const float*)d_in[0];
    float* out = (float*)d_out;

    dim3 block(32, YT_, 1);                 // 256 threads
    dim3 grid(3 * (H_ / YT_), NC_, 1);      // 48 x 32 = 1536 blocks
    sobel3d_kernel<<<grid, block>>>(x, out);
}

// round 9
// speedup vs baseline: 1.3983x; 1.3983x over previous
#include <cuda_runtime.h>
#include <cuda_bf16.h>
#include <cstdint>

// x = (N=2, C=16, D=96, H=128, W=128) fp32; out = concat(gx, gy, gz).
// cp.async 4-stage smem pipeline for the input plane stream; register z-rings;
// warp-shuffle x-halo; one wave of 512 CTAs.

#define W_   128
#define H_   128
#define D_   96
#define NC_  32
#define YT_  8
#define HW_  (H_ * W_)
#define CST_ (D_ * HW_)
#define V_   (NC_ * CST_)
#define ROWS_ (YT_ + 2)      // 10 rows per plane tile
#define STG_  4              // pipeline stages

__global__ __launch_bounds__(256, 5)
void sobel3d_kernel(const float* __restrict__ in, float* __restrict__ out) {
    __shared__ float sm[STG_][ROWS_][W_];

    const int lane = threadIdx.x;            // 0..31
    const int ty   = threadIdx.y;            // 0..7
    const int tid  = ty * 32 + lane;
    const int y0   = blockIdx.x * YT_;
    const int nc   = blockIdx.y;
    const int x4   = lane * 4;

    const float* src = in + nc * CST_;
    float* gx = out;
    const int obase = nc * CST_ + (y0 + ty) * W_ + x4;

    // Zero all stages once; y-OOB rows are never overwritten and stay zero.
    {
        float4 z4 = make_float4(0.f, 0.f, 0.f, 0.f);
        float4* smv = reinterpret_cast<float4*>(&sm[0][0][0]);
        #pragma unroll
        for (int i = 0; i < (STG_ * ROWS_ * W_ / 4 + 255) / 256; ++i) {
            int idx = tid + i * 256;
            if (idx < STG_ * ROWS_ * W_ / 4) smv[idx] = z4;
        }
    }
    __syncthreads();

    // Producer: copy plane p (rows y0-1..y0+8) into stage p&3 via cp.async.
    auto load_plane = [&](int p) {
        const int st = p & (STG_ - 1);
        const float* pl = src + p * HW_;
        for (int i = tid; i < ROWS_ * 32; i += 256) {      // 320 float4s
            const int row = i >> 5;
            const int c4  = (i & 31) * 4;
            const int gyy = y0 - 1 + row;
            if ((unsigned)gyy < (unsigned)H_) {
                const float* s = pl + gyy * W_ + c4;
                unsigned int d = (unsigned int)__cvta_generic_to_shared(&sm[st][row][c4]);
                asm volatile("cp.async.cg.shared.global [%0], [%1], 16;\n"
                             :: "r"(d), "l"(s));
            }
        }
        asm volatile("cp.async.commit_group;\n");
    };

    load_plane(0);
    load_plane(1);
    load_plane(2);

    float4 zz = make_float4(0.f, 0.f, 0.f, 0.f);
    float4 s_m = zz, s_0 = zz, d_m = zz, d_0 = zz;

    for (int p = 0; p < D_; ++p) {
        asm volatile("cp.async.wait_group 2;\n" ::: "memory");
        __syncthreads();

        const int st = p & (STG_ - 1);
        float4 rm = *reinterpret_cast<const float4*>(&sm[st][ty    ][x4]);
        float4 r0 = *reinterpret_cast<const float4*>(&sm[st][ty + 1][x4]);
        float4 rp = *reinterpret_cast<const float4*>(&sm[st][ty + 2][x4]);

        // keep the pipeline full before the compute/store chain
        if (p + 3 < D_) load_plane(p + 3);
        else asm volatile("cp.async.commit_group;\n");

        float4 s_p, d_p;
        d_p.x = rp.x - rm.x; d_p.y = rp.y - rm.y;
        d_p.z = rp.z - rm.z; d_p.w = rp.w - rm.w;
        s_p.x = rm.x + 2.f * r0.x + rp.x;
        s_p.y = rm.y + 2.f * r0.y + rp.y;
        s_p.z = rm.z + 2.f * r0.z + rp.z;
        s_p.w = rm.w + 2.f * r0.w + rp.w;

        if (p >= 1) {
            float4 Sz, Dz, Zc;
            Sz.x = s_m.x + 2.f * s_0.x + s_p.x;
            Sz.y = s_m.y + 2.f * s_0.y + s_p.y;
            Sz.z = s_m.z + 2.f * s_0.z + s_p.z;
            Sz.w = s_m.w + 2.f * s_0.w + s_p.w;
            Dz.x = d_m.x + 2.f * d_0.x + d_p.x;
            Dz.y = d_m.y + 2.f * d_0.y + d_p.y;
            Dz.z = d_m.z + 2.f * d_0.z + d_p.z;
            Dz.w = d_m.w + 2.f * d_0.w + d_p.w;
            Zc.x = s_p.x - s_m.x; Zc.y = s_p.y - s_m.y;
            Zc.z = s_p.z - s_m.z; Zc.w = s_p.w - s_m.w;

            float SzL = __shfl_up_sync(0xffffffffu, Sz.w, 1);
            float SzR = __shfl_down_sync(0xffffffffu, Sz.x, 1);
            float DzL = __shfl_up_sync(0xffffffffu, Dz.w, 1);
            float DzR = __shfl_down_sync(0xffffffffu, Dz.x, 1);
            float ZcL = __shfl_up_sync(0xffffffffu, Zc.w, 1);
            float ZcR = __shfl_down_sync(0xffffffffu, Zc.x, 1);
            if (lane == 0)  { SzL = 0.f; DzL = 0.f; ZcL = 0.f; }
            if (lane == 31) { SzR = 0.f; DzR = 0.f; ZcR = 0.f; }

            float4 vx, vy, vz;
            vx.x = Sz.y - SzL;  vx.y = Sz.z - Sz.x;
            vx.z = Sz.w - Sz.y; vx.w = SzR  - Sz.z;
            vy.x = DzL  + 2.f * Dz.x + Dz.y;
            vy.y = Dz.x + 2.f * Dz.y + Dz.z;
            vy.z = Dz.y + 2.f * Dz.z + Dz.w;
            vy.w = Dz.z + 2.f * Dz.w + DzR;
            vz.x = ZcL  + 2.f * Zc.x + Zc.y;
            vz.y = Zc.x + 2.f * Zc.y + Zc.z;
            vz.z = Zc.y + 2.f * Zc.z + Zc.w;
            vz.w = Zc.z + 2.f * Zc.w + ZcR;

            const int o = obase + (p - 1) * HW_;
            __stcs(reinterpret_cast<float4*>(gx + o), vx);
            __stcs(reinterpret_cast<float4*>(gx + V_ + o), vy);
            __stcs(reinterpret_cast<float4*>(gx + 2 * V_ + o), vz);
        }
        s_m = s_0; s_0 = s_p;
        d_m = d_0; d_0 = d_p;
    }

    // Final output plane oz = D-1 (plane D is zero).
    {
        float4 Sz, Dz, Zc;
        Sz.x = s_m.x + 2.f * s_0.x; Sz.y = s_m.y + 2.f * s_0.y;
        Sz.z = s_m.z + 2.f * s_0.z; Sz.w = s_m.w + 2.f * s_0.w;
        Dz.x = d_m.x + 2.f * d_0.x; Dz.y = d_m.y + 2.f * d_0.y;
        Dz.z = d_m.z + 2.f * d_0.z; Dz.w = d_m.w + 2.f * d_0.w;
        Zc.x = -s_m.x; Zc.y = -s_m.y; Zc.z = -s_m.z; Zc.w = -s_m.w;

        float SzL = __shfl_up_sync(0xffffffffu, Sz.w, 1);
        float SzR = __shfl_down_sync(0xffffffffu, Sz.x, 1);
        float DzL = __shfl_up_sync(0xffffffffu, Dz.w, 1);
        float DzR = __shfl_down_sync(0xffffffffu, Dz.x, 1);
        float ZcL = __shfl_up_sync(0xffffffffu, Zc.w, 1);
        float ZcR = __shfl_down_sync(0xffffffffu, Zc.x, 1);
        if (lane == 0)  { SzL = 0.f; DzL = 0.f; ZcL = 0.f; }
        if (lane == 31) { SzR = 0.f; DzR = 0.f; ZcR = 0.f; }

        float4 vx, vy, vz;
        vx.x = Sz.y - SzL;  vx.y = Sz.z - Sz.x;
        vx.z = Sz.w - Sz.y; vx.w = SzR  - Sz.z;
        vy.x = DzL  + 2.f * Dz.x + Dz.y;
        vy.y = Dz.x + 2.f * Dz.y + Dz.z;
        vy.z = Dz.y + 2.f * Dz.z + Dz.w;
        vy.w = Dz.z + 2.f * Dz.w + DzR;
        vz.x = ZcL  + 2.f * Zc.x + Zc.y;
        vz.y = Zc.x + 2.f * Zc.y + Zc.z;
        vz.z = Zc.y + 2.f * Zc.z + Zc.w;
        vz.w = Zc.z + 2.f * Zc.w + ZcR;

        const int o = obase + (D_ - 1) * HW_;
        __stcs(reinterpret_cast<float4*>(gx + o), vx);
        __stcs(reinterpret_cast<float4*>(gx + V_ + o), vy);
        __stcs(reinterpret_cast<float4*>(gx + 2 * V_ + o), vz);
    }
}

extern "C" void kernel_launch(void* const* d_in, const int* in_sizes, int n_in,
                              void* d_out, int out_size) {
    const float* x = (const float*)d_in[0];
    float* out = (float*)d_out;

    dim3 block(32, YT_, 1);            // 256 threads
    dim3 grid(H_ / YT_, NC_, 1);       // 512 blocks, one wave
    sobel3d_kernel<<<grid, block>>>(x, out);
}